// round 16
// baseline (speedup 1.0000x reference)
#include <cuda_runtime.h>
#include <cstdint>

// PARCOR (reflection) -> LPC coefficients (Levinson step-up), k: [2097152, 25] f32.
//
// Per row: a = k; for m in 2..24: a[1:m] += k[m] * a[1:m][::-1]
// k[m] == a[m] when step m runs, so the recursion is in-place on 25 registers.
//
// R16: small-block (128-thread, 12.8 KB tile) double-buffered TMA pipeline,
// persistent grid, STATIC strided tile assignment.
//   - 2 x 12.8 KB smem -> 8 blocks/SM -> ~16 concurrent tile streams per SM
//     (R14 showed DRAM% tracks streams/SM; R11's 12 streams beat R14's 4).
//   - Prefetch tile i+stride into the other buffer before waiting on tile i;
//     stores drain via bulk_group, buffer reuse guarded by wait_group.read.
//   - Strided assignment keeps loop bounds uniform across the block: no
//     atomics, no reset kernel, no smem flags.

#define ORDER_P1 25
#define ROWS 128
#define THREADS 128
#define TILE_FLOATS (ROWS * ORDER_P1)        // 3200
#define TILE_BYTES  (TILE_FLOATS * 4)        // 12800
#define SMEM_BYTES  (2 * TILE_BYTES)         // 25600 -> dynamic smem
#define GRID_BLOCKS (148 * 8)                // 1184 persistent blocks

extern __shared__ float sbuf[];              // [2][TILE_FLOATS]

__device__ __forceinline__ void mbar_wait(uint32_t s_mbar, uint32_t phase)
{
    uint32_t done;
    asm volatile(
        "{\n\t.reg .pred p;\n\t"
        "mbarrier.try_wait.parity.acquire.cta.shared::cta.b64 p, [%1], %2;\n\t"
        "selp.b32 %0, 1, 0, p;\n\t}"
        : "=r"(done) : "r"(s_mbar), "r"(phase) : "memory");
    while (!done) {
        asm volatile(
            "{\n\t.reg .pred p;\n\t"
            "mbarrier.try_wait.parity.acquire.cta.shared::cta.b64 p, [%1], %2, 0x989680;\n\t"
            "selp.b32 %0, 1, 0, p;\n\t}"
            : "=r"(done) : "r"(s_mbar), "r"(phase) : "memory");
    }
}

__global__ __launch_bounds__(THREADS)
void parcor_to_lpc_pipe128(const float* __restrict__ kin,
                           float* __restrict__ out,
                           int ntiles)
{
    __shared__ alignas(8) unsigned long long mbar[2];

    const int t = threadIdx.x;
    const int bid = blockIdx.x;
    const int stride = GRID_BLOCKS;

    float* buf[2] = { sbuf, sbuf + TILE_FLOATS };
    const uint32_t s_b[2] = { (uint32_t)__cvta_generic_to_shared(buf[0]),
                              (uint32_t)__cvta_generic_to_shared(buf[1]) };
    const uint32_t s_m[2] = { (uint32_t)__cvta_generic_to_shared(&mbar[0]),
                              (uint32_t)__cvta_generic_to_shared(&mbar[1]) };

    if (bid >= ntiles) return;               // (never taken for this shape)

    if (t == 0) {
        asm volatile("mbarrier.init.shared.b64 [%0], 1;" :: "r"(s_m[0]) : "memory");
        asm volatile("mbarrier.init.shared.b64 [%0], 1;" :: "r"(s_m[1]) : "memory");
        asm volatile("fence.proxy.async.shared::cta;" ::: "memory");

        // ---- prologue: load first tile into buf0 ----
        asm volatile("mbarrier.arrive.expect_tx.shared.b64 _, [%0], %1;"
                     :: "r"(s_m[0]), "r"((uint32_t)TILE_BYTES) : "memory");
        asm volatile(
            "cp.async.bulk.shared::cta.global.mbarrier::complete_tx::bytes "
            "[%0], [%1], %2, [%3];"
            :: "r"(s_b[0]), "l"(kin + (size_t)bid * TILE_FLOATS),
               "r"((uint32_t)TILE_BYTES), "r"(s_m[0])
            : "memory");
    }
    __syncthreads();

    uint32_t ph[2] = { 0u, 0u };
    int it = 0;

    #pragma unroll 1
    for (int tile = bid; tile < ntiles; tile += stride, it++) {
        const int j = it & 1;
        const int next = tile + stride;

        // ---- prefetch next tile into the other buffer ----
        if (t == 0 && next < ntiles) {
            // prior bulk store must have finished READING buf[j^1]
            asm volatile("cp.async.bulk.wait_group.read 0;" ::: "memory");
            asm volatile("mbarrier.arrive.expect_tx.shared.b64 _, [%0], %1;"
                         :: "r"(s_m[j ^ 1]), "r"((uint32_t)TILE_BYTES) : "memory");
            asm volatile(
                "cp.async.bulk.shared::cta.global.mbarrier::complete_tx::bytes "
                "[%0], [%1], %2, [%3];"
                :: "r"(s_b[j ^ 1]), "l"(kin + (size_t)next * TILE_FLOATS),
                   "r"((uint32_t)TILE_BYTES), "r"(s_m[j ^ 1])
                : "memory");
        }

        // ---- wait for current tile's load ----
        mbar_wait(s_m[j], ph[j]);
        ph[j] ^= 1u;

        // ---- compute own row (stride-25 smem: gcd(25,32)=1, conflict-free) ----
        float* curb = buf[j];
        float a[ORDER_P1];
        #pragma unroll
        for (int x = 0; x < ORDER_P1; x++) a[x] = curb[t * ORDER_P1 + x];

        #pragma unroll
        for (int m = 2; m <= 24; m++) {
            const float km = a[m];          // == original k[m]
            #pragma unroll
            for (int jj = 1; 2 * jj < m; jj++) {
                const float x = a[jj];
                const float y = a[m - jj];
                a[jj]     = fmaf(km, y, x);
                a[m - jj] = fmaf(km, x, y);
            }
            if ((m & 1) == 0) {
                const int jj = m >> 1;
                a[jj] = fmaf(km, a[jj], a[jj]);   // midpoint: a[j] *= (1+km)
            }
        }

        #pragma unroll
        for (int x = 0; x < ORDER_P1; x++) curb[t * ORDER_P1 + x] = a[x];

        // generic-proxy STS visible to async-proxy bulk store
        asm volatile("fence.proxy.async.shared::cta;" ::: "memory");
        __syncthreads();

        // ---- issue store of current tile (drains in background) ----
        if (t == 0) {
            asm volatile(
                "cp.async.bulk.global.shared::cta.bulk_group [%0], [%1], %2;"
                :: "l"(out + (size_t)tile * TILE_FLOATS), "r"(s_b[j]),
                   "r"((uint32_t)TILE_BYTES)
                : "memory");
            asm volatile("cp.async.bulk.commit_group;" ::: "memory");
        }
    }

    // ---- drain last stores before block exit ----
    if (t == 0) {
        asm volatile("cp.async.bulk.wait_group 0;" ::: "memory");
    }
}

extern "C" void kernel_launch(void* const* d_in, const int* in_sizes, int n_in,
                              void* d_out, int out_size)
{
    const float* k = (const float*)d_in[0];
    float* out = (float*)d_out;

    const int nrows = in_sizes[0] / ORDER_P1;      // 2097152
    const int ntiles = nrows / ROWS;               // 16384

    static bool attr_set = false;
    if (!attr_set) {
        cudaFuncSetAttribute(parcor_to_lpc_pipe128,
                             cudaFuncAttributeMaxDynamicSharedMemorySize,
                             SMEM_BYTES);
        attr_set = true;
    }

    parcor_to_lpc_pipe128<<<GRID_BLOCKS, THREADS, SMEM_BYTES>>>(k, out, ntiles);
}

// round 17
// speedup vs baseline: 1.1636x; 1.1636x over previous
#include <cuda_runtime.h>
#include <cstdint>

// PARCOR (reflection) -> LPC coefficients (Levinson step-up), k: [2097152, 25] f32.
//
// Per row: a = k; for m in 2..24: a[1:m] += k[m] * a[1:m][::-1]
// k[m] == a[m] when step m runs, so the recursion is in-place on 25 registers.
//
// R17: fully warp-independent TMA streaming. 256-thread blocks, 8 blocks/SM
// (64 warps = 100% occupancy cap), single 25.6 KB smem tile — but every warp
// owns a private 3200 B slice, private mbarrier, and issues its own
// cp.async.bulk load AND store. No __syncthreads at all: 64 independent
// warp-streams per SM whose load/compute/store phases de-correlate and keep
// DRAM busy continuously. (Post-mortem of R11..R16: DRAM% tracks resident
// warp count; every smem-hungry double-buffer lost more occupancy than the
// overlap gained.)

#define ORDER_P1 25
#define THREADS 256
#define WARPS 8
#define ROWS_PER_WARP 32
#define WARP_FLOATS (ROWS_PER_WARP * ORDER_P1)   // 800
#define WARP_BYTES  (WARP_FLOATS * 4)            // 3200 (16B multiple)
#define TILE_FLOATS (WARPS * WARP_FLOATS)        // 6400
#define ROWS (WARPS * ROWS_PER_WARP)             // 256 rows per block

__device__ __forceinline__ void mbar_wait(uint32_t s_mbar, uint32_t phase)
{
    uint32_t done;
    asm volatile(
        "{\n\t.reg .pred p;\n\t"
        "mbarrier.try_wait.parity.acquire.cta.shared::cta.b64 p, [%1], %2;\n\t"
        "selp.b32 %0, 1, 0, p;\n\t}"
        : "=r"(done) : "r"(s_mbar), "r"(phase) : "memory");
    while (!done) {
        asm volatile(
            "{\n\t.reg .pred p;\n\t"
            "mbarrier.try_wait.parity.acquire.cta.shared::cta.b64 p, [%1], %2, 0x989680;\n\t"
            "selp.b32 %0, 1, 0, p;\n\t}"
            : "=r"(done) : "r"(s_mbar), "r"(phase) : "memory");
    }
}

__global__ __launch_bounds__(THREADS)
void parcor_to_lpc_warpstream(const float* __restrict__ kin,
                              float* __restrict__ out)
{
    __shared__ alignas(128) float tile[TILE_FLOATS];
    __shared__ alignas(8) unsigned long long mbar[WARPS];

    const int t = threadIdx.x;
    const int w = t >> 5;
    const int l = t & 31;

    float* ws = tile + w * WARP_FLOATS;
    const uint32_t s_ws = (uint32_t)__cvta_generic_to_shared(ws);
    const uint32_t s_mb = (uint32_t)__cvta_generic_to_shared(&mbar[w]);

    const size_t gbase = (size_t)blockIdx.x * TILE_FLOATS + (size_t)w * WARP_FLOATS;

    // ---- warp-private mbarrier init (only this warp ever touches it) ----
    if (l == 0) {
        asm volatile("mbarrier.init.shared.b64 [%0], 1;" :: "r"(s_mb) : "memory");
        asm volatile("fence.proxy.async.shared::cta;" ::: "memory");
    }
    __syncwarp();

    // ---- warp-private bulk load: 3200 B slice ----
    if (l == 0) {
        asm volatile("mbarrier.arrive.expect_tx.shared.b64 _, [%0], %1;"
                     :: "r"(s_mb), "r"((uint32_t)WARP_BYTES) : "memory");
        asm volatile(
            "cp.async.bulk.shared::cta.global.mbarrier::complete_tx::bytes "
            "[%0], [%1], %2, [%3];"
            :: "r"(s_ws), "l"(kin + gbase), "r"((uint32_t)WARP_BYTES), "r"(s_mb)
            : "memory");
    }

    // ---- all lanes of this warp wait for this warp's slice ----
    mbar_wait(s_mb, 0u);

    // ---- load own row (stride-25 smem: gcd(25,32)=1 -> conflict-free) ----
    float a[ORDER_P1];
    #pragma unroll
    for (int x = 0; x < ORDER_P1; x++) a[x] = ws[l * ORDER_P1 + x];

    // ---- Levinson step-up, fully unrolled in registers ----
    #pragma unroll
    for (int m = 2; m <= 24; m++) {
        const float km = a[m];              // == original k[m]
        #pragma unroll
        for (int j = 1; 2 * j < m; j++) {
            const float x = a[j];
            const float y = a[m - j];
            a[j]     = fmaf(km, y, x);
            a[m - j] = fmaf(km, x, y);
        }
        if ((m & 1) == 0) {
            const int j = m >> 1;
            a[j] = fmaf(km, a[j], a[j]);     // midpoint: a[j] *= (1 + km)
        }
    }

    // ---- write own row back in place (intra-thread WAR only) ----
    #pragma unroll
    for (int x = 0; x < ORDER_P1; x++) ws[l * ORDER_P1 + x] = a[x];

    // generic-proxy STS must be visible to async-proxy bulk store
    asm volatile("fence.proxy.async.shared::cta;" ::: "memory");
    __syncwarp();

    // ---- warp-private bulk store: fires as soon as THIS warp is done ----
    if (l == 0) {
        asm volatile(
            "cp.async.bulk.global.shared::cta.bulk_group [%0], [%1], %2;"
            :: "l"(out + gbase), "r"(s_ws), "r"((uint32_t)WARP_BYTES)
            : "memory");
        asm volatile("cp.async.bulk.commit_group;" ::: "memory");
        asm volatile("cp.async.bulk.wait_group 0;" ::: "memory");
    }
}

extern "C" void kernel_launch(void* const* d_in, const int* in_sizes, int n_in,
                              void* d_out, int out_size)
{
    const float* k = (const float*)d_in[0];
    float* out = (float*)d_out;

    const int nrows = in_sizes[0] / ORDER_P1;   // 2097152, divisible by 256
    const int grid = nrows / ROWS;              // 8192

    parcor_to_lpc_warpstream<<<grid, THREADS>>>(k, out);
}